// round 5
// baseline (speedup 1.0000x reference)
#include <cuda_runtime.h>

#define N_NODES 100000
#define N_EDGES 3200000
#define EPS_F 1e-6f

// Scratch (no allocations allowed in kernel_launch).
__device__ float  g_node_sum[N_NODES];
__device__ double g_acc[8];
// g_acc[0] = sum p0
// g_acc[1] = sum p1
// g_acc[2] = sum p0^2
// g_acc[3] = sum p1^2
// g_acc[4] = sum node_sum^2

__device__ __forceinline__ float warp_sum(float v) {
    #pragma unroll
    for (int o = 16; o; o >>= 1) v += __shfl_xor_sync(0xffffffffu, v, o);
    return v;
}

__global__ void zero_kernel() {
    int i = blockIdx.x * blockDim.x + threadIdx.x;
    if (i < N_NODES) g_node_sum[i] = 0.0f;
    if (i < 8)       g_acc[i] = 0.0;
}

// One pass over edges: scatter currents into node sums, and accumulate the
// four moment sums for the variance term.
// edge_index arrives as int32 (harness downcasts the reference's int64).
__global__ void __launch_bounds__(256) edge_kernel(
    const float* __restrict__ node_features,
    const int*   __restrict__ edge_index,
    const float* __restrict__ edge_logits,
    const float2* __restrict__ edge_params)
{
    float s0 = 0.f, s1 = 0.f, q0 = 0.f, q1 = 0.f;

    const int stride = gridDim.x * blockDim.x;
    for (int e = blockIdx.x * blockDim.x + threadIdx.x; e < N_EDGES; e += stride) {
        int src = edge_index[e];
        int dst = edge_index[N_EDGES + e];
        float2 p  = edge_params[e];
        float  lg = edge_logits[e];

        // sigmoid
        float prob = 1.0f / (1.0f + __expf(-lg));

        float vs = node_features[src * 4];   // column 0, row stride 4
        float vd = node_features[dst * 4];
        float vdiff = fabsf(vs - vd);
        float cur = vdiff / (p.x + p.y + EPS_F) * prob;

        atomicAdd(&g_node_sum[dst],  cur);
        atomicAdd(&g_node_sum[src], -cur);

        s0 += p.x;  s1 += p.y;
        q0 += p.x * p.x;  q1 += p.y * p.y;
    }

    // Block reduction of the 4 moment accumulators.
    __shared__ float sm[4][8];   // 8 warps @ 256 threads
    int lane = threadIdx.x & 31;
    int wid  = threadIdx.x >> 5;

    s0 = warp_sum(s0); s1 = warp_sum(s1); q0 = warp_sum(q0); q1 = warp_sum(q1);
    if (lane == 0) { sm[0][wid] = s0; sm[1][wid] = s1; sm[2][wid] = q0; sm[3][wid] = q1; }
    __syncthreads();
    if (wid == 0) {
        float a = (lane < 8) ? sm[0][lane] : 0.f;
        float b = (lane < 8) ? sm[1][lane] : 0.f;
        float c = (lane < 8) ? sm[2][lane] : 0.f;
        float d = (lane < 8) ? sm[3][lane] : 0.f;
        a = warp_sum(a); b = warp_sum(b); c = warp_sum(c); d = warp_sum(d);
        if (lane == 0) {
            atomicAdd(&g_acc[0], (double)a);
            atomicAdd(&g_acc[1], (double)b);
            atomicAdd(&g_acc[2], (double)c);
            atomicAdd(&g_acc[3], (double)d);
        }
    }
}

__global__ void __launch_bounds__(256) node_kernel() {
    float acc = 0.f;
    const int stride = gridDim.x * blockDim.x;
    for (int i = blockIdx.x * blockDim.x + threadIdx.x; i < N_NODES; i += stride) {
        float v = g_node_sum[i];
        acc += v * v;
    }
    __shared__ float sm[8];
    int lane = threadIdx.x & 31;
    int wid  = threadIdx.x >> 5;
    acc = warp_sum(acc);
    if (lane == 0) sm[wid] = acc;
    __syncthreads();
    if (wid == 0) {
        float a = (lane < 8) ? sm[lane] : 0.f;
        a = warp_sum(a);
        if (lane == 0) atomicAdd(&g_acc[4], (double)a);
    }
}

__global__ void final_kernel(float* __restrict__ out) {
    double sum0 = g_acc[0], sum1 = g_acc[1];
    double sq0  = g_acc[2], sq1  = g_acc[3];
    double nsq  = g_acc[4];

    const double E = (double)N_EDGES;
    double var0 = (sq0 - sum0 * sum0 / E) / (E - 1.0);
    double var1 = (sq1 - sum1 * sum1 / E) / (E - 1.0);
    double kvl = 0.5 * (var0 + var1);
    double kcl = nsq / (double)N_NODES;
    out[0] = (float)(kcl + kvl);
}

extern "C" void kernel_launch(void* const* d_in, const int* in_sizes, int n_in,
                              void* d_out, int out_size)
{
    const float*  node_features = (const float*)d_in[0];
    const int*    edge_index    = (const int*)d_in[1];
    const float*  edge_logits   = (const float*)d_in[2];
    const float2* edge_params   = (const float2*)d_in[3];
    float* out = (float*)d_out;

    (void)in_sizes; (void)n_in; (void)out_size;

    zero_kernel<<<(N_NODES + 255) / 256, 256>>>();

    // ~8.4 edges per thread; keeps double-atomic contention at ~1.5k ops
    // per accumulator.
    edge_kernel<<<1480, 256>>>(node_features, edge_index, edge_logits, edge_params);

    node_kernel<<<(N_NODES + 255) / 256, 256>>>();

    final_kernel<<<1, 1>>>(out);
}